// round 10
// baseline (speedup 1.0000x reference)
#include <cuda_runtime.h>
#include <math.h>
#include <stdint.h>

// ---------------------------------------------------------------- constants
#define NUM_CODES 4096
#define D 64
#define HW 4096
#define N_VEC 32768

#define OFF_ZQ   0
#define OFF_LOSS 2097152
#define OFF_PERP 2097153
#define OFF_ENC  2097154ULL
#define ENC_ELEMS 134217728ULL
#define OFF_IND  (OFF_ENC + ENC_ELEMS)
#define OUT_FULL (OFF_IND + N_VEC)
#define BETA 0.25f

#define NCH 128              // codes per chunk
#define NCHUNKS 32
#define NPAIR 64             // code pairs per chunk
#define MROWS 64             // rows per compute CTA
#define NZERO 148            // zeroing CTAs (one wave worth of slots)
#define NCOMP (N_VEC / MROWS)   // 512 compute CTAs

// smem layout (bytes)
#define SMZ 0                // Zs[64][66] floats = 16896
#define SMW 16896            // Wp[32][64] float4 = 32768
#define SMQ 49664            // wsq chunk [128] floats = 512
#define SM_TOTAL 50176

// ---------------------------------------------------------------- scratch
__device__ float g_wsq[NUM_CODES];
__device__ int   g_idx[N_VEC];
__device__ int   g_counts[NUM_CODES];
__device__ float g_loss;
// Pre-interleaved W image: [chunk][k2][pair] float4 =
//   (w[2p][2k2], w[2p+1][2k2], w[2p][2k2+1], w[2p+1][2k2+1])
__device__ float4 g_wpimg[NCHUNKS * 32 * NPAIR];   // 1 MB

// ---------------------------------------------------------------- f32x2 helpers
__device__ __forceinline__ unsigned long long fma2(unsigned long long a,
                                                   unsigned long long b,
                                                   unsigned long long c) {
    unsigned long long d;
    asm("fma.rn.f32x2 %0, %1, %2, %3;" : "=l"(d) : "l"(a), "l"(b), "l"(c));
    return d;
}
__device__ __forceinline__ unsigned long long pack_dup(float v) {
    unsigned long long d;
    asm("mov.b64 %0, {%1, %1};" : "=l"(d) : "f"(v));
    return d;
}
__device__ __forceinline__ void unpack2(unsigned long long v, float& lo, float& hi) {
    asm("mov.b64 {%0, %1}, %2;" : "=f"(lo), "=f"(hi) : "l"(v));
}

// ---------------------------------------------------------------- small kernels
__global__ void wsq_kernel(const float* __restrict__ w) {
    int gw = (blockIdx.x * blockDim.x + threadIdx.x) >> 5;
    int lane = threadIdx.x & 31;
    if (gw >= NUM_CODES) return;
    const float* row = w + gw * D;
    float s = 0.f;
    #pragma unroll
    for (int j = 0; j < D; j += 32) { float v = row[j + lane]; s += v * v; }
    #pragma unroll
    for (int o = 16; o; o >>= 1) s += __shfl_xor_sync(0xffffffffu, s, o);
    if (lane == 0) g_wsq[gw] = 0.5f * s;
}

__global__ void init_kernel() {
    int t = blockIdx.x * blockDim.x + threadIdx.x;
    if (t < NUM_CODES) g_counts[t] = 0;
    if (t == 0) g_loss = 0.f;
}

// Build the interleaved W image
__global__ __launch_bounds__(256) void prep_wp(const float* __restrict__ w) {
    int ch = blockIdx.x;
    int cbase = ch * NCH;
    for (int e = threadIdx.x; e < 32 * NPAIR; e += 256) {
        int k2 = e >> 6, p = e & 63;
        const float* c0 = w + (size_t)(cbase + 2 * p) * D + 2 * k2;
        const float* c1 = c0 + D;
        float2 va = *(const float2*)c0;
        float2 vb = *(const float2*)c1;
        g_wpimg[ch * 2048 + e] = make_float4(va.x, vb.x, va.y, vb.y);
    }
}

// ---------------------------------------------------------------- main argmax (FFMA2)
// Grid = NZERO zeroing CTAs (DRAM-bound, exit early) + NCOMP compute CTAs.
// Compute CTA: 128 threads, tile = 64 rows x all 4096 codes (32 chunks of 128).
// Thread micro-tile: 8 rows x 4 code-pairs, f32x2 accumulators.
__global__ __launch_bounds__(128, 4) void argmax_f2(const float* __restrict__ z,
                                                    float* __restrict__ enc,
                                                    int do_zero) {
    int tid = threadIdx.x;

    if (blockIdx.x < NZERO) {
        // ---- zeroing CTA: clear a slice of the one-hot encodings buffer ----
        // enc is only 8-byte aligned (OFF_ENC*4 = 8388616). Zero a 2-float
        // head to reach 16B alignment, then float4 the body, then the tail.
        if (!do_zero) return;
        float4* p4 = (float4*)(enc + 2);                  // 16B-aligned
        const size_t body4 = (ENC_ELEMS - 4) / 4;         // whole float4s in body
        size_t per = (body4 + NZERO - 1) / NZERO;
        size_t lo = (size_t)blockIdx.x * per;
        size_t hi = lo + per; if (hi > body4) hi = body4;
        float4 zv = make_float4(0.f, 0.f, 0.f, 0.f);
        for (size_t i = lo + tid; i < hi; i += 128) p4[i] = zv;
        if (blockIdx.x == 0 && tid < 2) {
            enc[tid] = 0.f;                               // head
            enc[ENC_ELEMS - 2 + tid] = 0.f;               // tail
        }
        return;
    }

    extern __shared__ char smem[];
    float*  Zs   = (float*)(smem + SMZ);     // [64][66]
    float4* Wp   = (float4*)(smem + SMW);    // [32][64]
    float*  wsqS = (float*)(smem + SMQ);     // [128]

    int tx = tid & 15, ty = tid >> 4;        // ty in 0..7
    int nbase = (blockIdx.x - NZERO) * MROWS;
    int b = nbase >> 12, hw0 = nbase & 4095;
    const float* zb = z + (size_t)b * 262144 + hw0;

    // Z transpose into smem: Zs[r][c] = z[b, c, hw0 + r]
    for (int e = tid; e < MROWS * 64; e += 128) {
        int c = e >> 6, r = e & 63;
        Zs[r * 66 + c] = zb[(size_t)c * HW + r];
    }

    float best[8];
    int   bidx[8];
    #pragma unroll
    for (int i = 0; i < 8; i++) { best[i] = -3.0e38f; bidx[i] = 0; }

    for (int ch = 0; ch < NCHUNKS; ch++) {
        __syncthreads();
        {
            const float4* src = g_wpimg + ch * 2048;
            #pragma unroll
            for (int i = 0; i < 16; i++) Wp[tid + 128 * i] = src[tid + 128 * i];
        }
        wsqS[tid] = g_wsq[ch * NCH + tid];
        __syncthreads();

        unsigned long long acc[8][4];
        #pragma unroll
        for (int i = 0; i < 8; i++)
            #pragma unroll
            for (int j = 0; j < 4; j++) acc[i][j] = 0ull;

        #pragma unroll 2
        for (int k2 = 0; k2 < 32; k2++) {
            unsigned long long b0[4], b1[4];
            #pragma unroll
            for (int j = 0; j < 4; j++) {
                ulonglong2 lv = *(ulonglong2*)&Wp[k2 * 64 + tx + 16 * j];
                b0[j] = lv.x; b1[j] = lv.y;
            }
            #pragma unroll
            for (int i = 0; i < 8; i++) {
                float2 az = *(float2*)&Zs[(ty + 8 * i) * 66 + 2 * k2];
                unsigned long long a0 = pack_dup(az.x);
                unsigned long long a1 = pack_dup(az.y);
                #pragma unroll
                for (int j = 0; j < 4; j++) {
                    acc[i][j] = fma2(a0, b0[j], acc[i][j]);
                    acc[i][j] = fma2(a1, b1[j], acc[i][j]);
                }
            }
        }

        // fused argmax epilogue: score = z.w - 0.5||w||^2
        #pragma unroll
        for (int j = 0; j < 4; j++) {
            int p = tx + 16 * j;
            float2 q2 = *(float2*)&wsqS[2 * p];
            int code = ch * NCH + 2 * p;
            #pragma unroll
            for (int i = 0; i < 8; i++) {
                float lo, hi;
                unpack2(acc[i][j], lo, hi);
                float s0 = lo - q2.x;
                float s1 = hi - q2.y;
                if (s0 > best[i]) { best[i] = s0; bidx[i] = code; }
                if (s1 > best[i]) { best[i] = s1; bidx[i] = code + 1; }
            }
        }
    }

    // reduce across the 16 tx lanes (width-16 segments hold same rows)
    #pragma unroll
    for (int i = 0; i < 8; i++) {
        float v = best[i];
        int ix = bidx[i];
        #pragma unroll
        for (int o = 8; o; o >>= 1) {
            float ov = __shfl_down_sync(0xffffffffu, v, o, 16);
            int   oi = __shfl_down_sync(0xffffffffu, ix, o, 16);
            if (ov > v || (ov == v && oi < ix)) { v = ov; ix = oi; }
        }
        if (tx == 0) g_idx[nbase + ty + 8 * i] = ix;
    }
}

// ---------------------------------------------------------------- pass2 + finalize
__global__ __launch_bounds__(256) void pass2_kernel(const float* __restrict__ z,
                                                    const float* __restrict__ w,
                                                    float* __restrict__ out) {
    int n = blockIdx.x * 256 + threadIdx.x;
    int idx = g_idx[n];
    int b = n >> 12, hw = n & 4095;
    const float* zb = z + (size_t)b * 262144 + hw;
    float* zq = out + OFF_ZQ + (size_t)b * 262144 + hw;
    const float* wr = w + (size_t)idx * D;
    float ls = 0.f;
    #pragma unroll 8
    for (int c = 0; c < D; c++) {
        float wv = wr[c];
        float zv = zb[(size_t)c * HW];
        float d = wv - zv;
        ls += d * d;
        zq[(size_t)c * HW] = wv;
    }
    out[OFF_ENC + (size_t)n * NUM_CODES + (size_t)idx] = 1.0f;
    out[OFF_IND + (size_t)n] = (float)idx;
    atomicAdd(&g_counts[idx], 1);
    __shared__ float red[256];
    red[threadIdx.x] = ls;
    __syncthreads();
    for (int s = 128; s; s >>= 1) {
        if (threadIdx.x < s) red[threadIdx.x] += red[threadIdx.x + s];
        __syncthreads();
    }
    if (threadIdx.x == 0) atomicAdd(&g_loss, red[0]);
}

__global__ __launch_bounds__(256) void pass2_zq_only(const float* __restrict__ w,
                                                     float* __restrict__ out) {
    int n = blockIdx.x * 256 + threadIdx.x;
    int idx = g_idx[n];
    int b = n >> 12, hw = n & 4095;
    float* zq = out + (size_t)b * 262144 + hw;
    const float* wr = w + (size_t)idx * D;
    #pragma unroll 8
    for (int c = 0; c < D; c++) zq[(size_t)c * HW] = wr[c];
}

__global__ void finalize_kernel(float* __restrict__ out) {
    __shared__ float red[256];
    float s = 0.f;
    for (int k = threadIdx.x; k < NUM_CODES; k += 256) {
        float p = (float)g_counts[k] * (1.0f / 32768.0f);
        s += p * logf(p + 1e-10f);
    }
    red[threadIdx.x] = s;
    __syncthreads();
    for (int st = 128; st; st >>= 1) {
        if (threadIdx.x < st) red[threadIdx.x] += red[threadIdx.x + st];
        __syncthreads();
    }
    if (threadIdx.x == 0) {
        out[OFF_PERP] = expf(-red[0]);
        out[OFF_LOSS] = BETA * g_loss * (1.0f / 2097152.0f);
    }
}

// ---------------------------------------------------------------- launch
extern "C" void kernel_launch(void* const* d_in, const int* in_sizes, int n_in,
                              void* d_out, int out_size) {
    const float* z = (const float*)d_in[0];
    const float* w = (const float*)d_in[1];
    float* out = (float*)d_out;

    cudaFuncSetAttribute(argmax_f2, cudaFuncAttributeMaxDynamicSharedMemorySize,
                         SM_TOTAL);

    int full = ((unsigned long long)out_size >= OUT_FULL);

    wsq_kernel<<<512, 256>>>(w);
    init_kernel<<<17, 256>>>();
    prep_wp<<<NCHUNKS, 256>>>(w);

    // zeroing CTAs first (exit in ~65us, freeing slots), compute CTAs after
    argmax_f2<<<NZERO + NCOMP, 128, SM_TOTAL>>>(z, out + OFF_ENC, full);

    if (full) {
        pass2_kernel<<<N_VEC / 256, 256>>>(z, w, out);
        finalize_kernel<<<1, 256>>>(out);
    } else {
        pass2_zq_only<<<N_VEC / 256, 256>>>(w, out);
    }
}

// round 12
// speedup vs baseline: 1.1256x; 1.1256x over previous
#include <cuda_runtime.h>
#include <math.h>
#include <stdint.h>

// ---------------------------------------------------------------- constants
#define NUM_CODES 4096
#define D 64
#define HW 4096
#define N_VEC 32768

#define OFF_ZQ   0
#define OFF_LOSS 2097152
#define OFF_PERP 2097153
#define OFF_ENC  2097154ULL
#define ENC_ELEMS 134217728ULL
#define OFF_IND  (OFF_ENC + ENC_ELEMS)
#define OUT_FULL (OFF_IND + N_VEC)
#define BETA 0.25f

#define NCH 128              // codes per chunk
#define NCHUNKS 32
#define MROWS 128            // rows per CTA
#define NCOMP (N_VEC / MROWS)   // 256 CTAs = one wave

// smem layout (bytes)
#define SMZ   0              // Zs[128][66] floats = 33792
#define SMW0  33792          // W buf 0: 2048 float4 = 32768
#define SMW1  66560          // W buf 1: 32768
#define SMQ0  99328          // wsq buf 0: 512
#define SMQ1  99840          // wsq buf 1: 512
#define SMIDX 100352         // idx_s[128] int = 512
#define SM_TOTAL 100864

// ---------------------------------------------------------------- scratch
__device__ float g_wsq[NUM_CODES];
__device__ int   g_counts[NUM_CODES];
__device__ float g_loss;
// Pre-interleaved W image: [chunk][k2][pair] float4 =
//   (w[2p][2k2], w[2p+1][2k2], w[2p][2k2+1], w[2p+1][2k2+1])
__device__ float4 g_wpimg[NCHUNKS * 32 * 64];   // 1 MB

// ---------------------------------------------------------------- helpers
__device__ __forceinline__ unsigned long long fma2(unsigned long long a,
                                                   unsigned long long b,
                                                   unsigned long long c) {
    unsigned long long d;
    asm("fma.rn.f32x2 %0, %1, %2, %3;" : "=l"(d) : "l"(a), "l"(b), "l"(c));
    return d;
}
__device__ __forceinline__ unsigned long long pack_dup(float v) {
    unsigned long long d;
    asm("mov.b64 %0, {%1, %1};" : "=l"(d) : "f"(v));
    return d;
}
__device__ __forceinline__ void unpack2(unsigned long long v, float& lo, float& hi) {
    asm("mov.b64 {%0, %1}, %2;" : "=f"(lo), "=f"(hi) : "l"(v));
}
__device__ __forceinline__ uint32_t smem_u32(const void* p) {
    uint32_t a;
    asm("{ .reg .u64 t; cvta.to.shared.u64 t, %1; cvt.u32.u64 %0, t; }" : "=r"(a) : "l"(p));
    return a;
}
__device__ __forceinline__ void cp16(uint32_t dst, const void* src) {
    asm volatile("cp.async.cg.shared.global [%0], [%1], 16;" :: "r"(dst), "l"(src));
}

// ---------------------------------------------------------------- prep (fused wsq+init+wimg)
__global__ __launch_bounds__(256) void prep_all(const float* __restrict__ w) {
    int tid = threadIdx.x;
    if (blockIdx.x < 32) {
        // build interleaved W image for chunk blockIdx.x
        int ch = blockIdx.x;
        int cbase = ch * NCH;
        for (int e = tid; e < 32 * 64; e += 256) {
            int k2 = e >> 6, p = e & 63;
            const float* c0 = w + (size_t)(cbase + 2 * p) * D + 2 * k2;
            const float* c1 = c0 + D;
            float2 va = *(const float2*)c0;
            float2 vb = *(const float2*)c1;
            g_wpimg[ch * 2048 + e] = make_float4(va.x, vb.x, va.y, vb.y);
        }
    } else {
        // wsq for 128 codes + zero counts
        int blk = blockIdx.x - 32;
        int lane = tid & 31, wp = tid >> 5;
        #pragma unroll
        for (int rep = 0; rep < 16; rep++) {
            int code = blk * 128 + rep * 8 + wp;
            const float* row = w + (size_t)code * D;
            float s = 0.f;
            #pragma unroll
            for (int j = 0; j < D; j += 32) { float v = row[j + lane]; s += v * v; }
            #pragma unroll
            for (int o = 16; o; o >>= 1) s += __shfl_xor_sync(0xffffffffu, s, o);
            if (lane == 0) g_wsq[code] = 0.5f * s;
        }
        if (tid < 128) g_counts[blk * 128 + tid] = 0;
        if (blk == 0 && tid == 0) g_loss = 0.f;
    }
}

// ---------------------------------------------------------------- main fused kernel
// 256 CTAs x 256 threads; tile = 128 rows x all 4096 codes.
// Thread micro-tile: 8 rows x 4 code-pairs, f32x2 accumulators.
// Fused: per-CTA encodings zeroing (own slice), zq/loss/one-hot/hist epilogue.
__global__ __launch_bounds__(256, 2) void argmax_f2(const float* __restrict__ z,
                                                    const float* __restrict__ w,
                                                    float* __restrict__ out,
                                                    int full) {
    extern __shared__ char smem[];
    float* Zs   = (float*)(smem + SMZ);      // [128][66]
    int*   idxS = (int*)(smem + SMIDX);      // [128]
    uint32_t sb = smem_u32(smem);

    int tid = threadIdx.x;
    int tx = tid & 15, ty = tid >> 4;        // ty in 0..15
    int nbase = blockIdx.x * MROWS;
    int b = nbase >> 12, hw0 = nbase & 4095;
    const float* zb = z + (size_t)b * 262144 + hw0;

    // per-CTA encodings slice (this CTA's 128 rows x 4096 codes)
    float* encs = out + OFF_ENC + (size_t)nbase * NUM_CODES;
    float4* enc4 = (float4*)(encs + 2);      // 16B-aligned body
    const float4 zero4 = make_float4(0.f, 0.f, 0.f, 0.f);

    // prologue: async-load W chunk 0 + wsq chunk 0
    {
        const float4* src = g_wpimg;
        #pragma unroll
        for (int i = 0; i < 8; i++)
            cp16(sb + SMW0 + (tid + 256 * i) * 16, src + tid + 256 * i);
        if (tid < 32) cp16(sb + SMQ0 + tid * 16, (const float4*)g_wsq + tid);
        asm volatile("cp.async.commit_group;" ::: "memory");
    }

    // Z transpose into smem: Zs[r][c] = z[b, c, hw0 + r]
    for (int e = tid; e < MROWS * 64; e += 256) {
        int c = e >> 7, r = e & 127;
        Zs[r * 66 + c] = zb[(size_t)c * HW + r];
    }

    if (full && tid < 2) {                   // enc head/tail floats
        encs[tid] = 0.f;
        encs[(size_t)MROWS * NUM_CODES - 2 + tid] = 0.f;
    }

    float best[8];
    int   bidx[8];
    #pragma unroll
    for (int i = 0; i < 8; i++) { best[i] = -3.0e38f; bidx[i] = 0; }

    for (int ch = 0; ch < NCHUNKS; ch++) {
        asm volatile("cp.async.wait_group 0;" ::: "memory");
        __syncthreads();

        int buf = ch & 1;
        float4* Wp   = (float4*)(smem + (buf ? SMW1 : SMW0));
        float*  wsqS = (float*)(smem + (buf ? SMQ1 : SMQ0));

        if (ch + 1 < NCHUNKS) {              // prefetch next chunk
            uint32_t wdst = sb + (buf ? SMW0 : SMW1);
            uint32_t qdst = sb + (buf ? SMQ0 : SMQ1);
            const float4* src = g_wpimg + (ch + 1) * 2048;
            #pragma unroll
            for (int i = 0; i < 8; i++)
                cp16(wdst + (tid + 256 * i) * 16, src + tid + 256 * i);
            if (tid < 32)
                cp16(qdst + tid * 16, (const float4*)(g_wsq + (ch + 1) * 128) + tid);
            asm volatile("cp.async.commit_group;" ::: "memory");
        }

        // fire-and-forget zeroing of own encodings slice (16 STG.128/thread)
        if (full) {
            #pragma unroll
            for (int s = 0; s < 16; s++) {
                int i = ch * 16 + s;                     // 0..511
                size_t idx = (size_t)i * 256 + tid;
                if (idx < ((size_t)MROWS * NUM_CODES - 4) / 4) enc4[idx] = zero4;
            }
        }

        unsigned long long acc[8][4];
        #pragma unroll
        for (int i = 0; i < 8; i++)
            #pragma unroll
            for (int j = 0; j < 4; j++) acc[i][j] = 0ull;

        #pragma unroll 2
        for (int k2 = 0; k2 < 32; k2++) {
            unsigned long long b0[4], b1[4];
            #pragma unroll
            for (int j = 0; j < 4; j++) {
                ulonglong2 lv = *(ulonglong2*)&Wp[k2 * 64 + tx + 16 * j];
                b0[j] = lv.x; b1[j] = lv.y;
            }
            #pragma unroll
            for (int i = 0; i < 8; i++) {
                float2 az = *(float2*)&Zs[(ty + 16 * i) * 66 + 2 * k2];
                unsigned long long a0 = pack_dup(az.x);
                unsigned long long a1 = pack_dup(az.y);
                #pragma unroll
                for (int j = 0; j < 4; j++) {
                    acc[i][j] = fma2(a0, b0[j], acc[i][j]);
                    acc[i][j] = fma2(a1, b1[j], acc[i][j]);
                }
            }
        }

        // fused argmax epilogue: score = z.w - 0.5||w||^2
        #pragma unroll
        for (int j = 0; j < 4; j++) {
            int p = tx + 16 * j;
            float2 q2 = *(float2*)&wsqS[2 * p];
            int code = ch * NCH + 2 * p;
            #pragma unroll
            for (int i = 0; i < 8; i++) {
                float lo, hi;
                unpack2(acc[i][j], lo, hi);
                float s0 = lo - q2.x;
                float s1 = hi - q2.y;
                if (s0 > best[i]) { best[i] = s0; bidx[i] = code; }
                if (s1 > best[i]) { best[i] = s1; bidx[i] = code + 1; }
            }
        }
    }

    // reduce across the 16 tx lanes (width-16 segments hold same rows)
    #pragma unroll
    for (int i = 0; i < 8; i++) {
        float v = best[i];
        int ix = bidx[i];
        #pragma unroll
        for (int o = 8; o; o >>= 1) {
            float ov = __shfl_down_sync(0xffffffffu, v, o, 16);
            int   oi = __shfl_down_sync(0xffffffffu, ix, o, 16);
            if (ov > v || (ov == v && oi < ix)) { v = ov; ix = oi; }
        }
        if (tx == 0) idxS[ty + 16 * i] = ix;
    }
    __syncthreads();   // idx_s ready; all reads of W buffers done; enc zero STGs ordered

    // ---- fused pass2 ----
    // phase A: gather selected codebook rows into smem (coalesced)
    float* wepi = (float*)(smem + SMW0);     // [128][65]
    for (int e = tid; e < MROWS * 64; e += 256) {
        int r = e >> 6, c = e & 63;          // consecutive tid -> consecutive c
        wepi[r * 65 + c] = w[(size_t)idxS[r] * D + c];
    }
    __syncthreads();

    // phase B: zq write (coalesced over rows) + loss
    float ls = 0.f;
    float* zq = out + OFF_ZQ + (size_t)b * 262144 + hw0;
    for (int e = tid; e < MROWS * 64; e += 256) {
        int c = e >> 7, r = e & 127;         // consecutive tid -> consecutive r
        float wv = wepi[r * 65 + c];
        if (full) {
            float d = wv - Zs[r * 66 + c];
            ls += d * d;
        }
        zq[(size_t)c * HW + r] = wv;
    }

    if (full) {
        // one-hot, indices, histogram (own rows only; slice already zeroed)
        if (tid < MROWS) {
            int idx = idxS[tid];
            encs[(size_t)tid * NUM_CODES + idx] = 1.0f;
            out[OFF_IND + (size_t)(nbase + tid)] = (float)idx;
            atomicAdd(&g_counts[idx], 1);
        }
        // block-reduce loss
        __shared__ float red[256];
        red[tid] = ls;
        __syncthreads();
        for (int s = 128; s; s >>= 1) {
            if (tid < s) red[tid] += red[tid + s];
            __syncthreads();
        }
        if (tid == 0) atomicAdd(&g_loss, red[0]);
    }
}

// ---------------------------------------------------------------- finalize
__global__ void finalize_kernel(float* __restrict__ out) {
    __shared__ float red[256];
    float s = 0.f;
    for (int k = threadIdx.x; k < NUM_CODES; k += 256) {
        float p = (float)g_counts[k] * (1.0f / 32768.0f);
        s += p * logf(p + 1e-10f);
    }
    red[threadIdx.x] = s;
    __syncthreads();
    for (int st = 128; st; st >>= 1) {
        if (threadIdx.x < st) red[threadIdx.x] += red[threadIdx.x + st];
        __syncthreads();
    }
    if (threadIdx.x == 0) {
        out[OFF_PERP] = expf(-red[0]);
        out[OFF_LOSS] = BETA * g_loss * (1.0f / 2097152.0f);
    }
}

// ---------------------------------------------------------------- launch
extern "C" void kernel_launch(void* const* d_in, const int* in_sizes, int n_in,
                              void* d_out, int out_size) {
    const float* z = (const float*)d_in[0];
    const float* w = (const float*)d_in[1];
    float* out = (float*)d_out;

    cudaFuncSetAttribute(argmax_f2, cudaFuncAttributeMaxDynamicSharedMemorySize,
                         SM_TOTAL);

    int full = ((unsigned long long)out_size >= OUT_FULL);

    prep_all<<<64, 256>>>(w);
    argmax_f2<<<NCOMP, 256, SM_TOTAL>>>(z, w, out, full);
    if (full) finalize_kernel<<<1, 256>>>(out);
}

// round 13
// speedup vs baseline: 1.3267x; 1.1786x over previous
#include <cuda_runtime.h>
#include <cuda_bf16.h>
#include <math.h>
#include <stdint.h>

// ---------------------------------------------------------------- constants
#define NUM_CODES 4096
#define D 64
#define HW 4096
#define N_VEC 32768

#define OFF_ZQ   0
#define OFF_LOSS 2097152
#define OFF_PERP 2097153
#define OFF_ENC  2097154ULL
#define ENC_ELEMS 134217728ULL
#define OFF_IND  (OFF_ENC + ENC_ELEMS)
#define OUT_FULL (OFF_IND + N_VEC)
#define BETA 0.25f

// 3-term bf16 split: [z_hi|z_lo|z_hi] . [w_hi|w_hi|w_lo]  (K = 192)
#define KSTEPS 12            // 192 / 16 per mma
#define ROW_BYTES 384        // 192 bf16
#define NCH 64               // codes per chunk
#define NCHUNKS 64
#define MROWS 128            // rows per CTA
#define A_TILE_BYTES 49152   // 128 x 384
#define B_TILE_BYTES 24576   // 64 x 384
#define TAU 0.005f           // fp32-fixup margin (split err bound ~5e-5)

// smem layout
#define SM_A 0
#define SM_B0 49152
#define SM_B1 73728
#define SM_WSQ 98304         // full wsq, 16 KB
#define SM_TOTAL 114688      // 112 KB -> 2 CTAs/SM

// ---------------------------------------------------------------- scratch
__device__ float g_wsq[NUM_CODES];
__device__ int   g_idx[N_VEC];
__device__ int   g_counts[NUM_CODES];
__device__ float g_loss;
__device__ int   g_nflag;
__device__ int   g_flag[N_VEC];
__device__ unsigned char g_zimg[256u * A_TILE_BYTES];  // 12.6 MB swizzled A tiles
__device__ unsigned char g_wimg[64u * B_TILE_BYTES];   // 1.57 MB swizzled B chunks

// ---------------------------------------------------------------- helpers
__device__ __forceinline__ uint32_t smem_u32(const void* p) {
    uint32_t a;
    asm("{ .reg .u64 t; cvta.to.shared.u64 t, %1; cvt.u32.u64 %0, t; }" : "=r"(a) : "l"(p));
    return a;
}
__device__ __forceinline__ void cp16(uint32_t dst, const void* src) {
    asm volatile("cp.async.cg.shared.global [%0], [%1], 16;" :: "r"(dst), "l"(src));
}
__device__ __forceinline__ void ldsm4(uint32_t& r0, uint32_t& r1, uint32_t& r2,
                                      uint32_t& r3, uint32_t addr) {
    asm volatile("ldmatrix.sync.aligned.m8n8.x4.shared.b16 {%0,%1,%2,%3}, [%4];"
                 : "=r"(r0), "=r"(r1), "=r"(r2), "=r"(r3) : "r"(addr));
}
__device__ __forceinline__ void mma16816(float* c, const uint32_t* a,
                                         uint32_t b0, uint32_t b1) {
    asm volatile("mma.sync.aligned.m16n8k16.row.col.f32.bf16.bf16.f32 "
                 "{%0,%1,%2,%3}, {%4,%5,%6,%7}, {%8,%9}, {%0,%1,%2,%3};"
                 : "+f"(c[0]), "+f"(c[1]), "+f"(c[2]), "+f"(c[3])
                 : "r"(a[0]), "r"(a[1]), "r"(a[2]), "r"(a[3]), "r"(b0), "r"(b1));
}
__device__ __forceinline__ uint32_t pack_hi(float a, float b) {
    __nv_bfloat162 h = __floats2bfloat162_rn(a, b);
    return *(uint32_t*)&h;
}
__device__ __forceinline__ float bf_res(float v) {   // v - bf16(v)
    __nv_bfloat16 h = __float2bfloat16(v);
    return v - __bfloat162float(h);
}

// ---------------------------------------------------------------- prep (all-in-one)
// blocks 0..255: A image tiles; 256..319: B chunk images; 320..351: wsq + init
__global__ __launch_bounds__(256) void prep_all(const float* __restrict__ z,
                                                const float* __restrict__ w) {
    __shared__ float Zs[128 * 65];
    int tid = threadIdx.x;

    if (blockIdx.x < 256) {
        int nbase = blockIdx.x * 128;
        int b = nbase >> 12, hw0 = nbase & 4095;
        const float* zb = z + (size_t)b * 262144 + hw0;
        for (int e = tid; e < 128 * 64; e += 256) {
            int c = e >> 7, r = e & 127;
            Zs[r * 65 + c] = zb[(size_t)c * HW + r];
        }
        __syncthreads();
        unsigned char* img = g_zimg + (size_t)blockIdx.x * A_TILE_BYTES;
        for (int e = tid; e < 128 * 96; e += 256) {
            int r = e / 96, p = e - r * 96;
            int k = p * 2;
            int src, lo;
            if (k < 64)      { src = k;       lo = 0; }
            else if (k < 128){ src = k - 64;  lo = 1; }
            else             { src = k - 128; lo = 0; }
            float v0 = Zs[r * 65 + src], v1 = Zs[r * 65 + src + 1];
            if (lo) { v0 = bf_res(v0); v1 = bf_res(v1); }
            uint32_t off = r * ROW_BYTES + (((k >> 3) ^ (r & 7)) << 4) + (k & 7) * 2;
            *(uint32_t*)(img + off) = pack_hi(v0, v1);
        }
    } else if (blockIdx.x < 320) {
        int ch = blockIdx.x - 256;
        unsigned char* img = g_wimg + (size_t)ch * B_TILE_BYTES;
        int cbase = ch * NCH;
        for (int e = tid; e < NCH * 96; e += 256) {
            int r = e / 96, p = e - r * 96;
            int k = p * 2;
            int src, lo;
            if (k < 64)      { src = k;       lo = 0; }
            else if (k < 128){ src = k - 64;  lo = 0; }
            else             { src = k - 128; lo = 1; }
            const float* wr = w + (size_t)(cbase + r) * D;
            float v0 = wr[src], v1 = wr[src + 1];
            if (lo) { v0 = bf_res(v0); v1 = bf_res(v1); }
            uint32_t off = r * ROW_BYTES + (((k >> 3) ^ (r & 7)) << 4) + (k & 7) * 2;
            *(uint32_t*)(img + off) = pack_hi(v0, v1);
        }
    } else {
        int blk = blockIdx.x - 320;
        int lane = tid & 31, wp = tid >> 5;
        #pragma unroll
        for (int rep = 0; rep < 16; rep++) {
            int code = blk * 128 + rep * 8 + wp;
            const float* row = w + (size_t)code * D;
            float s = 0.f;
            #pragma unroll
            for (int j = 0; j < D; j += 32) { float v = row[j + lane]; s += v * v; }
            #pragma unroll
            for (int o = 16; o; o >>= 1) s += __shfl_xor_sync(0xffffffffu, s, o);
            if (lane == 0) g_wsq[code] = 0.5f * s;
        }
        if (tid < 128) g_counts[blk * 128 + tid] = 0;
        if (blk == 0 && tid == 0) { g_loss = 0.f; g_nflag = 0; }
    }
}

// ---------------------------------------------------------------- main argmax (HMMA)
// 256 CTAs x 256 threads; 128 rows x 4096 codes (64 chunks of 64), K=192 split.
// Software-pipelined ldmatrix; fused per-CTA encodings zeroing.
__global__ __launch_bounds__(256, 2) void argmax_mma(float* __restrict__ out,
                                                     int full) {
    extern __shared__ char smem[];
    uint32_t sb = smem_u32(smem);
    int tid = threadIdx.x;
    int warp = tid >> 5, lane = tid & 31;
    int nbase = blockIdx.x * MROWS;
    float* wsq_s = (float*)(smem + SM_WSQ);

    // per-CTA encodings slice
    float* encs = out + OFF_ENC + (size_t)nbase * NUM_CODES;
    float4* enc4 = (float4*)(encs + 2);      // 16B-aligned body
    const float4 zero4 = make_float4(0.f, 0.f, 0.f, 0.f);

    // async-load A tile + B chunk 0 + full wsq
    const char* gA = (const char*)g_zimg + (size_t)blockIdx.x * A_TILE_BYTES;
    #pragma unroll
    for (int i = 0; i < 12; i++)
        cp16(sb + SM_A + (tid + 256 * i) * 16, gA + (size_t)(tid + 256 * i) * 16);
    #pragma unroll
    for (int i = 0; i < 6; i++)
        cp16(sb + SM_B0 + (tid + 256 * i) * 16, (const char*)g_wimg + (size_t)(tid + 256 * i) * 16);
    #pragma unroll
    for (int i = 0; i < 4; i++)
        cp16(sb + SM_WSQ + (tid + 256 * i) * 16, (const float4*)g_wsq + tid + 256 * i);
    asm volatile("cp.async.commit_group;" ::: "memory");

    if (full && tid < 2) {                   // enc head/tail floats
        encs[tid] = 0.f;
        encs[(size_t)MROWS * NUM_CODES - 2 + tid] = 0.f;
    }
    asm volatile("cp.async.wait_group 0;" ::: "memory");
    __syncthreads();

    // ldmatrix lane geometry (validated in R4)
    int grp = lane >> 3, l7 = lane & 7;
    int mw = warp * 16;
    int arow = mw + ((grp & 1) << 3) + l7;
    int acgrp = grp >> 1;
    uint32_t aRowAddr = sb + SM_A + arow * ROW_BYTES;
    int armask = arow & 7;
    int brow_off = ((grp >> 1) << 3) + l7;
    int bcgrp = grp & 1;
    int qcol = (lane & 3) * 2;

    float best0 = -3.0e38f, sec0 = -3.0e38f, best1 = -3.0e38f, sec1 = -3.0e38f;
    int idx0 = 0, idx1 = 0;

    for (int c = 0; c < NCHUNKS; c++) {
        uint32_t Bb = sb + ((c & 1) ? SM_B1 : SM_B0);
        if (c + 1 < NCHUNKS) {   // prefetch next chunk into other buffer
            uint32_t Bn = sb + (((c + 1) & 1) ? SM_B1 : SM_B0);
            const char* gBn = (const char*)g_wimg + (size_t)(c + 1) * B_TILE_BYTES;
            #pragma unroll
            for (int i = 0; i < 6; i++)
                cp16(Bn + (tid + 256 * i) * 16, gBn + (size_t)(tid + 256 * i) * 16);
            asm volatile("cp.async.commit_group;" ::: "memory");
        }

        // fire-and-forget zeroing of own encodings slice (8 STG.128/thread)
        if (full) {
            #pragma unroll
            for (int s = 0; s < 8; s++) {
                size_t idx = (size_t)(c * 8 + s) * 256 + tid;
                if (idx < ((size_t)MROWS * NUM_CODES - 4) / 4) enc4[idx] = zero4;
            }
        }

        float acc[8][4];
        #pragma unroll
        for (int j = 0; j < 8; j++) {
            acc[j][0] = 0.f; acc[j][1] = 0.f; acc[j][2] = 0.f; acc[j][3] = 0.f;
        }

        // software-pipelined mainloop: fragments for kt preloaded one stage ahead
        uint32_t a[4], bq[4][4];
        {
            int ck = acgrp;
            ldsm4(a[0], a[1], a[2], a[3], aRowAddr + ((ck ^ armask) << 4));
            int ckb = bcgrp;
            #pragma unroll
            for (int nb = 0; nb < 4; nb++) {
                int br = nb * 16 + brow_off;
                ldsm4(bq[nb][0], bq[nb][1], bq[nb][2], bq[nb][3],
                      Bb + br * ROW_BYTES + ((ckb ^ l7) << 4));
            }
        }
        #pragma unroll
        for (int kt = 0; kt < KSTEPS; kt++) {
            uint32_t an[4], bn[4][4];
            if (kt + 1 < KSTEPS) {
                int ck = 2 * (kt + 1) + acgrp;
                ldsm4(an[0], an[1], an[2], an[3], aRowAddr + ((ck ^ armask) << 4));
                int ckb = 2 * (kt + 1) + bcgrp;
                #pragma unroll
                for (int nb = 0; nb < 4; nb++) {
                    int br = nb * 16 + brow_off;
                    ldsm4(bn[nb][0], bn[nb][1], bn[nb][2], bn[nb][3],
                          Bb + br * ROW_BYTES + ((ckb ^ l7) << 4));
                }
            }
            #pragma unroll
            for (int nb = 0; nb < 4; nb++) {
                mma16816(acc[2 * nb],     a, bq[nb][0], bq[nb][1]);
                mma16816(acc[2 * nb + 1], a, bq[nb][2], bq[nb][3]);
            }
            if (kt + 1 < KSTEPS) {
                #pragma unroll
                for (int q = 0; q < 4; q++) a[q] = an[q];
                #pragma unroll
                for (int nb = 0; nb < 4; nb++)
                    #pragma unroll
                    for (int q = 0; q < 4; q++) bq[nb][q] = bn[nb][q];
            }
        }

        // fused argmax epilogue
        int codebase = c * NCH;
        #pragma unroll
        for (int j = 0; j < 8; j++) {
            int n = codebase + 8 * j + qcol;
            float q0 = wsq_s[n], q1 = wsq_s[n + 1];
            float s;
            s = acc[j][0] - q0;
            if (s > best0) { sec0 = best0; best0 = s; idx0 = n; } else sec0 = fmaxf(sec0, s);
            s = acc[j][1] - q1;
            if (s > best0) { sec0 = best0; best0 = s; idx0 = n + 1; } else sec0 = fmaxf(sec0, s);
            s = acc[j][2] - q0;
            if (s > best1) { sec1 = best1; best1 = s; idx1 = n; } else sec1 = fmaxf(sec1, s);
            s = acc[j][3] - q1;
            if (s > best1) { sec1 = best1; best1 = s; idx1 = n + 1; } else sec1 = fmaxf(sec1, s);
        }

        if (c + 1 < NCHUNKS) asm volatile("cp.async.wait_group 0;" ::: "memory");
        __syncthreads();
    }

    // quad reduce (lanes of a quad cover different cols, same rows)
    #pragma unroll
    for (int o = 1; o <= 2; o <<= 1) {
        float ob = __shfl_xor_sync(0xffffffffu, best0, o);
        int   oi = __shfl_xor_sync(0xffffffffu, idx0, o);
        float os = __shfl_xor_sync(0xffffffffu, sec0, o);
        if (ob > best0 || (ob == best0 && oi < idx0)) {
            sec0 = fmaxf(best0, os); best0 = ob; idx0 = oi;
        } else sec0 = fmaxf(sec0, ob);
        ob = __shfl_xor_sync(0xffffffffu, best1, o);
        oi = __shfl_xor_sync(0xffffffffu, idx1, o);
        os = __shfl_xor_sync(0xffffffffu, sec1, o);
        if (ob > best1 || (ob == best1 && oi < idx1)) {
            sec1 = fmaxf(best1, os); best1 = ob; idx1 = oi;
        } else sec1 = fmaxf(sec1, ob);
    }
    if ((lane & 3) == 0) {
        int r0 = nbase + mw + (lane >> 2);
        g_idx[r0] = idx0;
        if (best0 - sec0 < TAU) { int p = atomicAdd(&g_nflag, 1); g_flag[p] = r0; }
        int r1 = r0 + 8;
        g_idx[r1] = idx1;
        if (best1 - sec1 < TAU) { int p = atomicAdd(&g_nflag, 1); g_flag[p] = r1; }
    }
}

// ---------------------------------------------------------------- fp32 fixup
__global__ __launch_bounds__(256) void fixup_kernel(const float* __restrict__ z,
                                                    const float* __restrict__ w) {
    __shared__ float zl[64];
    __shared__ float sv[256];
    __shared__ int   si[256];
    int nf = g_nflag;
    for (int f = blockIdx.x; f < nf; f += gridDim.x) {
        int n = g_flag[f];
        int b = n >> 12, hw = n & 4095;
        if (threadIdx.x < 64)
            zl[threadIdx.x] = z[(size_t)b * 262144 + (size_t)threadIdx.x * HW + hw];
        __syncthreads();
        float best = -3.0e38f; int bidx = 0;
        for (int k = threadIdx.x; k < NUM_CODES; k += 256) {
            const float* wr = w + (size_t)k * D;
            float s = 0.f;
            #pragma unroll 8
            for (int d = 0; d < D; d++) s += zl[d] * wr[d];
            s -= g_wsq[k];
            if (s > best) { best = s; bidx = k; }
        }
        sv[threadIdx.x] = best; si[threadIdx.x] = bidx;
        __syncthreads();
        for (int st = 128; st; st >>= 1) {
            if (threadIdx.x < st) {
                float ov = sv[threadIdx.x + st]; int oi = si[threadIdx.x + st];
                if (ov > sv[threadIdx.x] ||
                    (ov == sv[threadIdx.x] && oi < si[threadIdx.x])) {
                    sv[threadIdx.x] = ov; si[threadIdx.x] = oi;
                }
            }
            __syncthreads();
        }
        if (threadIdx.x == 0) g_idx[n] = si[0];
        __syncthreads();
    }
}

// ---------------------------------------------------------------- pass2 + finalize
__global__ __launch_bounds__(256) void pass2_kernel(const float* __restrict__ z,
                                                    const float* __restrict__ w,
                                                    float* __restrict__ out) {
    int n = blockIdx.x * 256 + threadIdx.x;
    int idx = g_idx[n];
    int b = n >> 12, hw = n & 4095;
    const float* zb = z + (size_t)b * 262144 + hw;
    float* zq = out + OFF_ZQ + (size_t)b * 262144 + hw;
    const float* wr = w + (size_t)idx * D;
    float ls = 0.f;
    #pragma unroll 8
    for (int c = 0; c < D; c++) {
        float wv = wr[c];
        float zv = zb[(size_t)c * HW];
        float d = wv - zv;
        ls += d * d;
        zq[(size_t)c * HW] = wv;
    }
    out[OFF_ENC + (size_t)n * NUM_CODES + (size_t)idx] = 1.0f;
    out[OFF_IND + (size_t)n] = (float)idx;
    atomicAdd(&g_counts[idx], 1);
    __shared__ float red[256];
    red[threadIdx.x] = ls;
    __syncthreads();
    for (int s = 128; s; s >>= 1) {
        if (threadIdx.x < s) red[threadIdx.x] += red[threadIdx.x + s];
        __syncthreads();
    }
    if (threadIdx.x == 0) atomicAdd(&g_loss, red[0]);
}

__global__ __launch_bounds__(256) void pass2_zq_only(const float* __restrict__ w,
                                                     float* __restrict__ out) {
    int n = blockIdx.x * 256 + threadIdx.x;
    int idx = g_idx[n];
    int b = n >> 12, hw = n & 4095;
    float* zq = out + (size_t)b * 262144 + hw;
    const float* wr = w + (size_t)idx * D;
    #pragma unroll 8
    for (int c = 0; c < D; c++) zq[(size_t)c * HW] = wr[c];
}

__global__ void finalize_kernel(float* __restrict__ out) {
    __shared__ float red[256];
    float s = 0.f;
    for (int k = threadIdx.x; k < NUM_CODES; k += 256) {
        float p = (float)g_counts[k] * (1.0f / 32768.0f);
        s += p * logf(p + 1e-10f);
    }
    red[threadIdx.x] = s;
    __syncthreads();
    for (int st = 128; st; st >>= 1) {
        if (threadIdx.x < st) red[threadIdx.x] += red[threadIdx.x + st];
        __syncthreads();
    }
    if (threadIdx.x == 0) {
        out[OFF_PERP] = expf(-red[0]);
        out[OFF_LOSS] = BETA * g_loss * (1.0f / 2097152.0f);
    }
}

// ---------------------------------------------------------------- launch
extern "C" void kernel_launch(void* const* d_in, const int* in_sizes, int n_in,
                              void* d_out, int out_size) {
    const float* z = (const float*)d_in[0];
    const float* w = (const float*)d_in[1];
    float* out = (float*)d_out;

    cudaFuncSetAttribute(argmax_mma, cudaFuncAttributeMaxDynamicSharedMemorySize,
                         SM_TOTAL);

    int full = ((unsigned long long)out_size >= OUT_FULL);

    prep_all<<<352, 256>>>(z, w);
    argmax_mma<<<N_VEC / MROWS, 256, SM_TOTAL>>>(out, full);
    fixup_kernel<<<128, 256>>>(z, w);

    if (full) {
        pass2_kernel<<<N_VEC / 256, 256>>>(z, w, out);
        finalize_kernel<<<1, 256>>>(out);
    } else {
        pass2_zq_only<<<N_VEC / 256, 256>>>(w, out);
    }
}